// round 1
// baseline (speedup 1.0000x reference)
#include <cuda_runtime.h>

// bMomentumLIF: x [B=64, T=64, F=8192] fp32 -> spikes [B, T, F] fp32.
// Per-(b,f) recurrence over t:
//   u      = u_last * 0.5 + x[t]          (TAU = 2)
//   s      = (u - th >= 0) ? 1 : 0
//   m      = mt*m + (1-mt)*(u - u_last)
//   u_next = (u*lb + m*(1-lb)) * (1-s)
// Scalars momentum/lamb/thresholds arrive as 1-element device arrays.

#define B_DIM 64
#define T_DIM 64
#define F_DIM 8192
#define F4    (F_DIM / 4)   // 2048 float4 lanes per (b,t) row

__global__ __launch_bounds__(128, 8)
void lif_kernel(const float4* __restrict__ x,
                const float* __restrict__ p_mom,
                const float* __restrict__ p_lamb,
                const float* __restrict__ p_th,
                float4* __restrict__ out)
{
    const int f4 = blockIdx.x * blockDim.x + threadIdx.x;  // 0..F4-1
    const int b  = blockIdx.y;

    const float mt   = p_mom[0];
    const float lb   = p_lamb[0];
    const float th   = p_th[0];
    const float omt  = 1.0f - mt;   // (1 - momentum)
    const float olb  = 1.0f - lb;   // (1 - lamb)

    // base index of (b, t=0, f4) in float4 units
    size_t base = (size_t)b * T_DIM * F4 + (size_t)f4;

    float4 u_last = make_float4(0.f, 0.f, 0.f, 0.f);
    float4 m      = make_float4(0.f, 0.f, 0.f, 0.f);

    // one-deep explicit prefetch; unroll lets ptxas batch further loads ahead
    float4 xi = x[base];

    #pragma unroll 16
    for (int t = 0; t < T_DIM; ++t) {
        float4 xn;
        if (t + 1 < T_DIM) xn = x[base + (size_t)(t + 1) * F4];

        float4 s;

        // lane 0
        {
            float u  = fmaf(u_last.x, 0.5f, xi.x);
            float sp = (u - th >= 0.0f) ? 1.0f : 0.0f;
            float mn = fmaf(mt, m.x, omt * (u - u_last.x));
            m.x = mn;
            u_last.x = (fmaf(u, lb, mn * olb)) * (1.0f - sp);
            s.x = sp;
        }
        // lane 1
        {
            float u  = fmaf(u_last.y, 0.5f, xi.y);
            float sp = (u - th >= 0.0f) ? 1.0f : 0.0f;
            float mn = fmaf(mt, m.y, omt * (u - u_last.y));
            m.y = mn;
            u_last.y = (fmaf(u, lb, mn * olb)) * (1.0f - sp);
            s.y = sp;
        }
        // lane 2
        {
            float u  = fmaf(u_last.z, 0.5f, xi.z);
            float sp = (u - th >= 0.0f) ? 1.0f : 0.0f;
            float mn = fmaf(mt, m.z, omt * (u - u_last.z));
            m.z = mn;
            u_last.z = (fmaf(u, lb, mn * olb)) * (1.0f - sp);
            s.z = sp;
        }
        // lane 3
        {
            float u  = fmaf(u_last.w, 0.5f, xi.w);
            float sp = (u - th >= 0.0f) ? 1.0f : 0.0f;
            float mn = fmaf(mt, m.w, omt * (u - u_last.w));
            m.w = mn;
            u_last.w = (fmaf(u, lb, mn * olb)) * (1.0f - sp);
            s.w = sp;
        }

        out[base + (size_t)t * F4] = s;
        xi = xn;
    }
}

extern "C" void kernel_launch(void* const* d_in, const int* in_sizes, int n_in,
                              void* d_out, int out_size)
{
    const float4* x    = (const float4*)d_in[0];
    const float*  mom  = (const float*)d_in[1];
    const float*  lamb = (const float*)d_in[2];
    const float*  th   = (const float*)d_in[3];
    float4*       out  = (float4*)d_out;

    dim3 block(128);
    dim3 grid(F4 / 128, B_DIM);   // (16, 64) = 1024 blocks
    lif_kernel<<<grid, block>>>(x, mom, lamb, th, out);
}

// round 2
// speedup vs baseline: 1.1374x; 1.1374x over previous
#include <cuda_runtime.h>

// bMomentumLIF: x [B=64, T=64, F=8192] fp32 -> spikes [B, T, F] fp32.
// Recurrence over t per (b,f) chain; chains independent.
// R2: float2 per thread (2x thread count -> 13.8 blocks/SM) + 2-deep prefetch,
// streaming cache hints. Goal: move off the DRAM-latency wall onto the BW ceiling.

#define B_DIM 64
#define T_DIM 64
#define F_DIM 8192
#define F2    (F_DIM / 2)   // 4096 float2 lanes per (b,t) row

__global__ __launch_bounds__(128, 16)
void lif_kernel(const float2* __restrict__ x,
                const float* __restrict__ p_mom,
                const float* __restrict__ p_lamb,
                const float* __restrict__ p_th,
                float2* __restrict__ out)
{
    const int f2 = blockIdx.x * blockDim.x + threadIdx.x;  // 0..F2-1
    const int b  = blockIdx.y;

    const float mt  = p_mom[0];
    const float lb  = p_lamb[0];
    const float th  = p_th[0];
    const float omt = 1.0f - mt;
    const float olb = 1.0f - lb;

    const float2* xp = x   + (size_t)b * T_DIM * F2 + (size_t)f2;
    float2*       op = out + (size_t)b * T_DIM * F2 + (size_t)f2;

    float2 u_last = make_float2(0.f, 0.f);
    float2 m      = make_float2(0.f, 0.f);

    // 2-deep prefetch pipeline (loads are address-independent of recurrence)
    float2 xi0 = __ldcs(xp);
    float2 xi1 = __ldcs(xp + F2);

    #pragma unroll 8
    for (int t = 0; t < T_DIM; ++t) {
        float2 xn;
        if (t + 2 < T_DIM) xn = __ldcs(xp + (size_t)(t + 2) * F2);

        float2 s;
        // lane x
        {
            float u  = fmaf(u_last.x, 0.5f, xi0.x);
            float sp = (u - th >= 0.0f) ? 1.0f : 0.0f;
            float mn = fmaf(mt, m.x, omt * (u - u_last.x));
            m.x = mn;
            u_last.x = fmaf(u, lb, mn * olb) * (1.0f - sp);
            s.x = sp;
        }
        // lane y
        {
            float u  = fmaf(u_last.y, 0.5f, xi0.y);
            float sp = (u - th >= 0.0f) ? 1.0f : 0.0f;
            float mn = fmaf(mt, m.y, omt * (u - u_last.y));
            m.y = mn;
            u_last.y = fmaf(u, lb, mn * olb) * (1.0f - sp);
            s.y = sp;
        }

        __stcs(op + (size_t)t * F2, s);

        xi0 = xi1;
        xi1 = xn;
    }
}

extern "C" void kernel_launch(void* const* d_in, const int* in_sizes, int n_in,
                              void* d_out, int out_size)
{
    const float2* x    = (const float2*)d_in[0];
    const float*  mom  = (const float*)d_in[1];
    const float*  lamb = (const float*)d_in[2];
    const float*  th   = (const float*)d_in[3];
    float2*       out  = (float2*)d_out;

    dim3 block(128);
    dim3 grid(F2 / 128, B_DIM);   // (32, 64) = 2048 blocks
    lif_kernel<<<grid, block>>>(x, mom, lamb, th, out);
}